// round 3
// baseline (speedup 1.0000x reference)
#include <cuda_runtime.h>

// ---------------------------------------------------------------------------
// SkinDeformNet: linear blend skinning.
// Kernel A (rig): Rodrigues + kinematic chain -> Rs, Jt, compact A12 scratch.
// Kernel B (pts): 2 pts/thread, row-3 eliminated (T row3 == [0,0,0,1]),
//                 A read via warp-uniform global loads (L1 sector dedup),
//                 weights software-pipelined in 4-joint chunks (low regs).
// ---------------------------------------------------------------------------

#define MAX_B  64
#define PTS_BLOCK 256
#define SPAN (PTS_BLOCK * 2)   // 512 points per block

// compact A: 12 floats (3x4 rows) per joint
__device__ __align__(16) float g_A[MAX_B * 24 * 12];

__device__ const int c_par[24]   = {-1,0,0,0,1,2,3,4,5,6,7,8,9,9,9,12,13,14,16,17,18,19,20,21};
__device__ const int c_depth[24] = { 0,1,1,1,2,2,2,3,3,3,4,4,4,4,4, 5, 5, 5, 6, 6, 7, 7, 8, 8};

// ============================= Kernel A: rig ===============================
__global__ void rig_kernel(const float* __restrict__ Js,
                           const float* __restrict__ poses,
                           float* __restrict__ outRs,
                           float* __restrict__ outJt)
{
    const int b = blockIdx.x;
    const int j = threadIdx.x;      // 32 threads, j<24 active

    __shared__ float sJ[24][3];
    __shared__ float sRes[24][12];  // 3x4 rows of the chained transform

    float R[9];
    if (j < 24) {
        float rx = poses[b*72 + j*3 + 0];
        float ry = poses[b*72 + j*3 + 1];
        float rz = poses[b*72 + j*3 + 2];
        float ang = sqrtf(rx*rx + ry*ry + rz*rz) + 1e-8f;
        float inv = 1.0f / ang;
        float x = rx*inv, y = ry*inv, z = rz*inv;
        float s = sinf(ang), c = cosf(ang);
        float o = 1.0f - c;
        R[0] = 1.0f - o*(y*y + z*z);
        R[1] = -s*z + o*(x*y);
        R[2] =  s*y + o*(x*z);
        R[3] =  s*z + o*(x*y);
        R[4] = 1.0f - o*(x*x + z*z);
        R[5] = -s*x + o*(y*z);
        R[6] = -s*y + o*(x*z);
        R[7] =  s*x + o*(y*z);
        R[8] = 1.0f - o*(x*x + y*y);
        #pragma unroll
        for (int i = 0; i < 9; i++) outRs[b*216 + j*9 + i] = R[i];
        sJ[j][0] = Js[b*72 + j*3 + 0];
        sJ[j][1] = Js[b*72 + j*3 + 1];
        sJ[j][2] = Js[b*72 + j*3 + 2];
    }
    __syncthreads();

    float res[12];
    const int dj = (j < 24) ? c_depth[j] : -1;
    for (int lv = 0; lv < 9; lv++) {
        if (dj == lv) {
            if (j == 0) {
                res[0]=R[0]; res[1]=R[1]; res[2] =R[2]; res[3] =sJ[0][0];
                res[4]=R[3]; res[5]=R[4]; res[6] =R[5]; res[7] =sJ[0][1];
                res[8]=R[6]; res[9]=R[7]; res[10]=R[8]; res[11]=sJ[0][2];
            } else {
                int p = c_par[j];
                float tx = sJ[j][0]-sJ[p][0], ty = sJ[j][1]-sJ[p][1], tz = sJ[j][2]-sJ[p][2];
                #pragma unroll
                for (int r = 0; r < 3; r++) {
                    float p0 = sRes[p][r*4+0], p1 = sRes[p][r*4+1];
                    float p2 = sRes[p][r*4+2], p3 = sRes[p][r*4+3];
                    res[r*4+0] = p0*R[0] + p1*R[3] + p2*R[6];
                    res[r*4+1] = p0*R[1] + p1*R[4] + p2*R[7];
                    res[r*4+2] = p0*R[2] + p1*R[5] + p2*R[8];
                    res[r*4+3] = p0*tx   + p1*ty   + p2*tz + p3;
                }
            }
            #pragma unroll
            for (int i = 0; i < 12; i++) sRes[j][i] = res[i];
        }
        __syncthreads();
    }

    if (j < 24) {
        float Jx = sJ[j][0], Jy = sJ[j][1], Jz = sJ[j][2];
        float* A = &g_A[(b*24 + j) * 12];
        #pragma unroll
        for (int r = 0; r < 3; r++) {
            A[r*4+0] = res[r*4+0];
            A[r*4+1] = res[r*4+1];
            A[r*4+2] = res[r*4+2];
            A[r*4+3] = res[r*4+3] - (res[r*4+0]*Jx + res[r*4+1]*Jy + res[r*4+2]*Jz);
            outJt[b*72 + j*3 + r] = res[r*4+3];
        }
    }
}

// ============================= Kernel B: points ============================
typedef unsigned long long ull;

__device__ __forceinline__ ull fma2(ull a, ull b, ull c)
{
    ull d;
    asm("fma.rn.f32x2 %0, %1, %2, %3;" : "=l"(d) : "l"(a), "l"(b), "l"(c));
    return d;
}

__device__ __forceinline__ ull pack2(float v)
{
    ull d;
    asm("mov.b64 %0, {%1, %2};" : "=l"(d) : "f"(v), "f"(v));
    return d;
}

__device__ __forceinline__ void ld_arow(const float* kp, ull& a0, ull& a1,
                                        ull& a2, ull& a3, ull& a4, ull& a5)
{
    asm volatile("ld.global.nc.v2.b64 {%0, %1}, [%2];"    : "=l"(a0), "=l"(a1) : "l"(kp));
    asm volatile("ld.global.nc.v2.b64 {%0, %1}, [%2+16];" : "=l"(a2), "=l"(a3) : "l"(kp));
    asm volatile("ld.global.nc.v2.b64 {%0, %1}, [%2+32];" : "=l"(a4), "=l"(a5) : "l"(kp));
}

// accumulate both points over all 24 joints, weights pipelined in 4-k chunks
template<bool SAME>
__device__ __forceinline__ void lbs_accum(const float* __restrict__ A0,
                                          const float* __restrict__ A1,
                                          const float4* __restrict__ w0v,
                                          const float4* __restrict__ w1v,
                                          ull* acc0, ull* acc1)
{
    float4 cw0 = __ldg(w0v + 0);
    float4 cw1 = __ldg(w1v + 0);
    #pragma unroll 1
    for (int j = 0; j < 6; j++) {
        float4 nw0, nw1;
        if (j < 5) { nw0 = __ldg(w0v + j + 1); nw1 = __ldg(w1v + j + 1); }
        const float cc0[4] = {cw0.x, cw0.y, cw0.z, cw0.w};
        const float cc1[4] = {cw1.x, cw1.y, cw1.z, cw1.w};
        const float* Aj0 = A0 + j * 48;
        const float* Aj1 = A1 + j * 48;
        #pragma unroll
        for (int c = 0; c < 4; c++) {
            ull a0,a1,a2,a3,a4,a5;
            ld_arow(Aj0 + c*12, a0,a1,a2,a3,a4,a5);
            ull ww0 = pack2(cc0[c]);
            acc0[0] = fma2(ww0, a0, acc0[0]);
            acc0[1] = fma2(ww0, a1, acc0[1]);
            acc0[2] = fma2(ww0, a2, acc0[2]);
            acc0[3] = fma2(ww0, a3, acc0[3]);
            acc0[4] = fma2(ww0, a4, acc0[4]);
            acc0[5] = fma2(ww0, a5, acc0[5]);
            ull ww1 = pack2(cc1[c]);
            if (SAME) {
                acc1[0] = fma2(ww1, a0, acc1[0]);
                acc1[1] = fma2(ww1, a1, acc1[1]);
                acc1[2] = fma2(ww1, a2, acc1[2]);
                acc1[3] = fma2(ww1, a3, acc1[3]);
                acc1[4] = fma2(ww1, a4, acc1[4]);
                acc1[5] = fma2(ww1, a5, acc1[5]);
            } else {
                ull e0,e1,e2,e3,e4,e5;
                ld_arow(Aj1 + c*12, e0,e1,e2,e3,e4,e5);
                acc1[0] = fma2(ww1, e0, acc1[0]);
                acc1[1] = fma2(ww1, e1, acc1[1]);
                acc1[2] = fma2(ww1, e2, acc1[2]);
                acc1[3] = fma2(ww1, e3, acc1[3]);
                acc1[4] = fma2(ww1, e4, acc1[4]);
                acc1[5] = fma2(ww1, e5, acc1[5]);
            }
        }
        cw0 = nw0; cw1 = nw1;
    }
}

__device__ __forceinline__ void store_point(float* __restrict__ outP,
                                            float* __restrict__ outT,
                                            const float* __restrict__ ps,
                                            int n, const ull* acc)
{
    float* Tp = outT + (size_t)n * 16;
    asm volatile("st.global.v2.b64 [%0],    {%1, %2};" :: "l"(Tp), "l"(acc[0]), "l"(acc[1]) : "memory");
    asm volatile("st.global.v2.b64 [%0+16], {%1, %2};" :: "l"(Tp), "l"(acc[2]), "l"(acc[3]) : "memory");
    asm volatile("st.global.v2.b64 [%0+32], {%1, %2};" :: "l"(Tp), "l"(acc[4]), "l"(acc[5]) : "memory");
    asm volatile("st.global.v4.f32 [%0+48], {%1, %2, %3, %4};"
                 :: "l"(Tp), "f"(0.0f), "f"(0.0f), "f"(0.0f), "f"(1.0f) : "memory");

    float t[12];
    #pragma unroll
    for (int i = 0; i < 6; i++)
        asm("mov.b64 {%0, %1}, %2;" : "=f"(t[2*i]), "=f"(t[2*i+1]) : "l"(acc[i]));

    float px = __ldg(ps + (size_t)n*3 + 0);
    float py = __ldg(ps + (size_t)n*3 + 1);
    float pz = __ldg(ps + (size_t)n*3 + 2);
    outP[(size_t)n*3 + 0] = t[0]*px + t[1]*py + t[2] *pz + t[3];
    outP[(size_t)n*3 + 1] = t[4]*px + t[5]*py + t[6] *pz + t[7];
    outP[(size_t)n*3 + 2] = t[8]*px + t[9]*py + t[10]*pz + t[11];
}

__global__ void __launch_bounds__(PTS_BLOCK, 3)
pts_kernel(const float* __restrict__ ps,
           const float* __restrict__ ws,
           const void*  __restrict__ batch_raw,
           float* __restrict__ outP,
           float* __restrict__ outT,
           int N)
{
    const int tid  = threadIdx.x;
    const int base = blockIdx.x * SPAN;
    const int n0   = base + tid;
    if (n0 >= N) return;
    const int n1s  = n0 + PTS_BLOCK;
    const bool have1 = (n1s < N);
    const int n1   = have1 ? n1s : n0;

    const int*       b32 = (const int*)batch_raw;
    const long long* b64 = (const long long*)batch_raw;

    // dtype probe: batch sorted, max ~B-1 (>0). If int64, the last 32-bit word
    // is a (zero) high half; if int32 it is the (nonzero) max value.
    const bool is64 = (__ldg(b32 + (N - 1)) == 0);

    const int b0 = is64 ? (int)__ldg(b64 + n0) : __ldg(b32 + n0);
    const int b1 = is64 ? (int)__ldg(b64 + n1) : __ldg(b32 + n1);

    const float4* w0v = reinterpret_cast<const float4*>(ws + (size_t)n0 * 24);
    const float4* w1v = reinterpret_cast<const float4*>(ws + (size_t)n1 * 24);

    const float* A0 = g_A + (size_t)b0 * 288;
    const float* A1 = g_A + (size_t)b1 * 288;

    ull acc0[6], acc1[6];
    #pragma unroll
    for (int i = 0; i < 6; i++) { acc0[i] = 0ull; acc1[i] = 0ull; }

    if (b0 == b1) {
        lbs_accum<true >(A0, A1, w0v, w1v, acc0, acc1);
    } else {
        lbs_accum<false>(A0, A1, w0v, w1v, acc0, acc1);
    }

    store_point(outP, outT, ps, n0, acc0);
    if (have1) store_point(outP, outT, ps, n1, acc1);
}

// =============================== launch ====================================
extern "C" void kernel_launch(void* const* d_in, const int* in_sizes, int n_in,
                              void* d_out, int out_size)
{
    const float* ps    = (const float*)d_in[0];
    const float* Js    = (const float*)d_in[1];
    const float* ws    = (const float*)d_in[2];
    const float* poses = (const float*)d_in[3];
    const void*  batch = d_in[4];

    const int N = in_sizes[0] / 3;
    int B = in_sizes[3] / 72;
    if (B > MAX_B) B = MAX_B;

    float* out   = (float*)d_out;
    float* outP  = out;                                  // N*3
    float* outT  = outP + (size_t)N * 3;                 // N*16
    float* outRs = outT + (size_t)N * 16;                // B*216
    float* outJt = outRs + (size_t)B * 216;              // B*72

    rig_kernel<<<B, 32>>>(Js, poses, outRs, outJt);

    const int blocks = (N + SPAN - 1) / SPAN;
    pts_kernel<<<blocks, PTS_BLOCK>>>(ps, ws, batch, outP, outT, N);
}

// round 4
// speedup vs baseline: 1.1456x; 1.1456x over previous
#include <cuda_runtime.h>

// ---------------------------------------------------------------------------
// SkinDeformNet: linear blend skinning.
// Kernel A (rig): Rodrigues + kinematic chain -> Rs, Jt, compact A12 scratch.
// Kernel B (pts): 2 pts/thread sharing one smem-A stream; row 3 of T is
//                 constant [0,0,0,1]; all loads are compiler-visible (no
//                 volatile asm) so ptxas can batch/pipeline them.
// ---------------------------------------------------------------------------

#define MAX_B  64
#define NB_MAX 4
#define PTS_BLOCK 256
#define SPAN (PTS_BLOCK * 2)   // 512 points per block

typedef unsigned long long ull;

// compact A: 12 floats (3x4 rows) per joint => 288 floats (1152 B) per batch
__device__ __align__(16) float g_A[MAX_B * 24 * 12];

__device__ const int c_par[24]   = {-1,0,0,0,1,2,3,4,5,6,7,8,9,9,9,12,13,14,16,17,18,19,20,21};
__device__ const int c_depth[24] = { 0,1,1,1,2,2,2,3,3,3,4,4,4,4,4, 5, 5, 5, 6, 6, 7, 7, 8, 8};

// ============================= Kernel A: rig ===============================
__global__ void rig_kernel(const float* __restrict__ Js,
                           const float* __restrict__ poses,
                           float* __restrict__ outRs,
                           float* __restrict__ outJt)
{
    const int b = blockIdx.x;
    const int j = threadIdx.x;      // 32 threads, j<24 active

    __shared__ float sJ[24][3];
    __shared__ float sRes[24][12];  // 3x4 rows of the chained transform

    float R[9];
    if (j < 24) {
        float rx = poses[b*72 + j*3 + 0];
        float ry = poses[b*72 + j*3 + 1];
        float rz = poses[b*72 + j*3 + 2];
        float ang = sqrtf(rx*rx + ry*ry + rz*rz) + 1e-8f;
        float inv = 1.0f / ang;
        float x = rx*inv, y = ry*inv, z = rz*inv;
        float s = sinf(ang), c = cosf(ang);
        float o = 1.0f - c;
        R[0] = 1.0f - o*(y*y + z*z);
        R[1] = -s*z + o*(x*y);
        R[2] =  s*y + o*(x*z);
        R[3] =  s*z + o*(x*y);
        R[4] = 1.0f - o*(x*x + z*z);
        R[5] = -s*x + o*(y*z);
        R[6] = -s*y + o*(x*z);
        R[7] =  s*x + o*(y*z);
        R[8] = 1.0f - o*(x*x + y*y);
        #pragma unroll
        for (int i = 0; i < 9; i++) outRs[b*216 + j*9 + i] = R[i];
        sJ[j][0] = Js[b*72 + j*3 + 0];
        sJ[j][1] = Js[b*72 + j*3 + 1];
        sJ[j][2] = Js[b*72 + j*3 + 2];
    }
    __syncthreads();

    float res[12];
    const int dj = (j < 24) ? c_depth[j] : -1;
    for (int lv = 0; lv < 9; lv++) {
        if (dj == lv) {
            if (j == 0) {
                res[0]=R[0]; res[1]=R[1]; res[2] =R[2]; res[3] =sJ[0][0];
                res[4]=R[3]; res[5]=R[4]; res[6] =R[5]; res[7] =sJ[0][1];
                res[8]=R[6]; res[9]=R[7]; res[10]=R[8]; res[11]=sJ[0][2];
            } else {
                int p = c_par[j];
                float tx = sJ[j][0]-sJ[p][0], ty = sJ[j][1]-sJ[p][1], tz = sJ[j][2]-sJ[p][2];
                #pragma unroll
                for (int r = 0; r < 3; r++) {
                    float p0 = sRes[p][r*4+0], p1 = sRes[p][r*4+1];
                    float p2 = sRes[p][r*4+2], p3 = sRes[p][r*4+3];
                    res[r*4+0] = p0*R[0] + p1*R[3] + p2*R[6];
                    res[r*4+1] = p0*R[1] + p1*R[4] + p2*R[7];
                    res[r*4+2] = p0*R[2] + p1*R[5] + p2*R[8];
                    res[r*4+3] = p0*tx   + p1*ty   + p2*tz + p3;
                }
            }
            #pragma unroll
            for (int i = 0; i < 12; i++) sRes[j][i] = res[i];
        }
        __syncthreads();
    }

    if (j < 24) {
        float Jx = sJ[j][0], Jy = sJ[j][1], Jz = sJ[j][2];
        float* A = &g_A[(b*24 + j) * 12];
        #pragma unroll
        for (int r = 0; r < 3; r++) {
            A[r*4+0] = res[r*4+0];
            A[r*4+1] = res[r*4+1];
            A[r*4+2] = res[r*4+2];
            A[r*4+3] = res[r*4+3] - (res[r*4+0]*Jx + res[r*4+1]*Jy + res[r*4+2]*Jz);
            outJt[b*72 + j*3 + r] = res[r*4+3];
        }
    }
}

// ============================= Kernel B: points ============================
__device__ __forceinline__ ull fma2(ull a, ull b, ull c)
{
    ull d;
    asm("fma.rn.f32x2 %0, %1, %2, %3;" : "=l"(d) : "l"(a), "l"(b), "l"(c));
    return d;
}

__device__ __forceinline__ ull pack2(float v)
{
    ull d;
    asm("mov.b64 %0, {%1, %2};" : "=l"(d) : "f"(v), "f"(v));
    return d;
}

// Accumulate T for two points sharing one A stream (A may be smem or global).
template<bool SAME>
__device__ __forceinline__ void lbs_accum(const ulonglong2* __restrict__ Ap0,
                                          const ulonglong2* __restrict__ Ap1,
                                          const float4* __restrict__ w0v,
                                          const float4* __restrict__ w1v,
                                          ull* acc0, ull* acc1)
{
    float4 cw0 = w0v[0];
    float4 cw1 = w1v[0];
    #pragma unroll 1
    for (int j = 0; j < 6; j++) {
        float4 nw0, nw1;
        if (j < 5) { nw0 = w0v[j + 1]; nw1 = w1v[j + 1]; }
        const float cc0[4] = {cw0.x, cw0.y, cw0.z, cw0.w};
        const float cc1[4] = {cw1.x, cw1.y, cw1.z, cw1.w};
        #pragma unroll
        for (int c = 0; c < 4; c++) {
            const int k = j * 4 + c;
            ulonglong2 p0 = Ap0[k*3 + 0];
            ulonglong2 p1 = Ap0[k*3 + 1];
            ulonglong2 p2 = Ap0[k*3 + 2];
            ull ww0 = pack2(cc0[c]);
            acc0[0] = fma2(ww0, p0.x, acc0[0]);
            acc0[1] = fma2(ww0, p0.y, acc0[1]);
            acc0[2] = fma2(ww0, p1.x, acc0[2]);
            acc0[3] = fma2(ww0, p1.y, acc0[3]);
            acc0[4] = fma2(ww0, p2.x, acc0[4]);
            acc0[5] = fma2(ww0, p2.y, acc0[5]);
            ull ww1 = pack2(cc1[c]);
            if (SAME) {
                acc1[0] = fma2(ww1, p0.x, acc1[0]);
                acc1[1] = fma2(ww1, p0.y, acc1[1]);
                acc1[2] = fma2(ww1, p1.x, acc1[2]);
                acc1[3] = fma2(ww1, p1.y, acc1[3]);
                acc1[4] = fma2(ww1, p2.x, acc1[4]);
                acc1[5] = fma2(ww1, p2.y, acc1[5]);
            } else {
                ulonglong2 q0 = Ap1[k*3 + 0];
                ulonglong2 q1 = Ap1[k*3 + 1];
                ulonglong2 q2 = Ap1[k*3 + 2];
                acc1[0] = fma2(ww1, q0.x, acc1[0]);
                acc1[1] = fma2(ww1, q0.y, acc1[1]);
                acc1[2] = fma2(ww1, q1.x, acc1[2]);
                acc1[3] = fma2(ww1, q1.y, acc1[3]);
                acc1[4] = fma2(ww1, q2.x, acc1[4]);
                acc1[5] = fma2(ww1, q2.y, acc1[5]);
            }
        }
        cw0 = nw0; cw1 = nw1;
    }
}

__device__ __forceinline__ void store_point(float* __restrict__ outP,
                                            float* __restrict__ outT,
                                            const float* __restrict__ ps,
                                            int n, const ull* acc)
{
    float t[12];
    #pragma unroll
    for (int i = 0; i < 6; i++)
        asm("mov.b64 {%0, %1}, %2;" : "=f"(t[2*i]), "=f"(t[2*i+1]) : "l"(acc[i]));

    float4* Tp = reinterpret_cast<float4*>(outT + (size_t)n * 16);
    Tp[0] = make_float4(t[0], t[1], t[2],  t[3]);
    Tp[1] = make_float4(t[4], t[5], t[6],  t[7]);
    Tp[2] = make_float4(t[8], t[9], t[10], t[11]);
    Tp[3] = make_float4(0.0f, 0.0f, 0.0f,  1.0f);

    float px = ps[(size_t)n*3 + 0];
    float py = ps[(size_t)n*3 + 1];
    float pz = ps[(size_t)n*3 + 2];
    outP[(size_t)n*3 + 0] = t[0]*px + t[1]*py + t[2] *pz + t[3];
    outP[(size_t)n*3 + 1] = t[4]*px + t[5]*py + t[6] *pz + t[7];
    outP[(size_t)n*3 + 2] = t[8]*px + t[9]*py + t[10]*pz + t[11];
}

__global__ void __launch_bounds__(PTS_BLOCK, 3)
pts_kernel(const float* __restrict__ ps,
           const float* __restrict__ ws,
           const void*  __restrict__ batch_raw,
           float* __restrict__ outP,
           float* __restrict__ outT,
           int N)
{
    __shared__ __align__(16) ull sA[NB_MAX * 144];   // 144 ull = 1152 B per batch
    __shared__ int s_info[3];                        // blo, nb, is64

    const int tid  = threadIdx.x;
    const int base = blockIdx.x * SPAN;

    const int*       b32 = (const int*)batch_raw;
    const long long* b64 = (const long long*)batch_raw;

    if (tid == 0) {
        // dtype probe: batch sorted, max ~B-1 (>0). If int64, the last 32-bit
        // word is a (zero) high half; if int32 it is the (nonzero) max value.
        int is64 = (b32[N - 1] == 0) ? 1 : 0;
        int last = base + SPAN - 1; if (last > N - 1) last = N - 1;
        int blo = is64 ? (int)b64[base] : b32[base];
        int bhi = is64 ? (int)b64[last] : b32[last];
        int nb  = bhi - blo + 1; if (nb > NB_MAX) nb = NB_MAX;
        s_info[0] = blo; s_info[1] = nb; s_info[2] = is64;
    }
    __syncthreads();
    const int blo  = s_info[0];
    const int nb   = s_info[1];
    const int is64 = s_info[2];

    // cooperative stage of A12 rows [blo, blo+nb) into smem
    {
        const ulonglong2* src = reinterpret_cast<const ulonglong2*>(g_A) + blo * 72;
        ulonglong2* dst = reinterpret_cast<ulonglong2*>(sA);
        for (int i = tid; i < nb * 72; i += PTS_BLOCK) dst[i] = __ldg(src + i);
    }
    __syncthreads();

    const int n0 = base + tid;
    if (n0 >= N) return;
    const int n1s = n0 + PTS_BLOCK;
    const bool have1 = (n1s < N);
    const int n1 = have1 ? n1s : n0;

    const int b0 = is64 ? (int)b64[n0] : b32[n0];
    const int b1 = is64 ? (int)b64[n1] : b32[n1];

    const float4* w0v = reinterpret_cast<const float4*>(ws + (size_t)n0 * 24);
    const float4* w1v = reinterpret_cast<const float4*>(ws + (size_t)n1 * 24);

    ull acc0[6], acc1[6];
    #pragma unroll
    for (int i = 0; i < 6; i++) { acc0[i] = 0ull; acc1[i] = 0ull; }

    const int local0 = b0 - blo;
    if (b0 == b1 && (unsigned)local0 < (unsigned)nb) {
        const ulonglong2* Ap = reinterpret_cast<const ulonglong2*>(sA + local0 * 144);
        lbs_accum<true>(Ap, Ap, w0v, w1v, acc0, acc1);
    } else {
        const ulonglong2* Ap0 = reinterpret_cast<const ulonglong2*>(g_A + (size_t)b0 * 288);
        const ulonglong2* Ap1 = reinterpret_cast<const ulonglong2*>(g_A + (size_t)b1 * 288);
        lbs_accum<false>(Ap0, Ap1, w0v, w1v, acc0, acc1);
    }

    store_point(outP, outT, ps, n0, acc0);
    if (have1) store_point(outP, outT, ps, n1, acc1);
}

// =============================== launch ====================================
extern "C" void kernel_launch(void* const* d_in, const int* in_sizes, int n_in,
                              void* d_out, int out_size)
{
    const float* ps    = (const float*)d_in[0];
    const float* Js    = (const float*)d_in[1];
    const float* ws    = (const float*)d_in[2];
    const float* poses = (const float*)d_in[3];
    const void*  batch = d_in[4];

    const int N = in_sizes[0] / 3;
    int B = in_sizes[3] / 72;
    if (B > MAX_B) B = MAX_B;

    float* out   = (float*)d_out;
    float* outP  = out;                                  // N*3
    float* outT  = outP + (size_t)N * 3;                 // N*16
    float* outRs = outT + (size_t)N * 16;                // B*216
    float* outJt = outRs + (size_t)B * 216;              // B*72

    rig_kernel<<<B, 32>>>(Js, poses, outRs, outJt);

    const int blocks = (N + SPAN - 1) / SPAN;
    pts_kernel<<<blocks, PTS_BLOCK>>>(ps, ws, batch, outP, outT, N);
}